// round 1
// baseline (speedup 1.0000x reference)
#include <cuda_runtime.h>

// out[row, f] = x[row, f] * sf^2,  sf = sum_m w_m(t) * coeffs[i-3+m, f]
// with i = floor(eig*7.5), t = eig*7.5 - i  (uniform knots linspace(0,2,16),
// cubic B-spline -> cardinal basis, only 4 nonzero weights).

#define F_CH 128
#define N_BASES 12
#define PAD_ROWS 18  // rows -3..14 mapped to 0..17 (i in [0,14], j+3 in [i..i+3] <= 17)

__global__ __launch_bounds__(256, 8)
void spline_filter_kernel(const float* __restrict__ x,
                          const float* __restrict__ eig,
                          const float* __restrict__ coef,
                          float* __restrict__ out,
                          int nrows)
{
    __shared__ float sc[PAD_ROWS * F_CH];  // zero-padded coeff table, 9 KB

    // Cooperative fill: rows [0,3) and [15,18) are zero, rows 3..14 = coeffs 0..11.
    for (int idx = threadIdx.x; idx < PAD_ROWS * F_CH; idx += blockDim.x) {
        int r = idx >> 7;          // padded row
        int c = idx & (F_CH - 1);  // channel
        int j = r - 3;
        float v = 0.0f;
        if (j >= 0 && j < N_BASES) v = coef[j * F_CH + c];
        sc[idx] = v;
    }
    __syncthreads();

    const int gwarp = (blockIdx.x * blockDim.x + threadIdx.x) >> 5;  // row index
    const int lane  = threadIdx.x & 31;                              // float4 index
    if (gwarp >= nrows) return;

    // Basis weights (every lane computes them; 1 redundant LDG broadcast per warp)
    float e = __ldg(eig + gwarp);
    float s = e * 7.5f;                    // 1/h, h = 2/15
    float fi = floorf(s);
    int   i  = (int)fi;
    i = min(max(i, 0), 14);
    float t = s - (float)i;
    float omt = 1.0f - t;
    float t2 = t * t;
    float w0 = omt * omt * omt * (1.0f / 6.0f);                     // j = i-3
    float w1 = ((3.0f * t - 6.0f) * t2 + 4.0f) * (1.0f / 6.0f);     // j = i-2
    float w2 = (((-3.0f * t + 3.0f) * t + 3.0f) * t + 1.0f) * (1.0f / 6.0f); // j = i-1
    float w3 = t * t2 * (1.0f / 6.0f);                              // j = i

    // Padded smem rows: weight m multiplies row (i + m)
    const float4* c0 = (const float4*)(sc + (i + 0) * F_CH);
    const float4* c1 = (const float4*)(sc + (i + 1) * F_CH);
    const float4* c2 = (const float4*)(sc + (i + 2) * F_CH);
    const float4* c3 = (const float4*)(sc + (i + 3) * F_CH);

    float4 a = c0[lane];
    float4 b = c1[lane];
    float4 c = c2[lane];
    float4 d = c3[lane];

    const float4* xrow = (const float4*)(x + (size_t)gwarp * F_CH);
    float4 xv = xrow[lane];

    float4 sf;
    sf.x = w0 * a.x + w1 * b.x + w2 * c.x + w3 * d.x;
    sf.y = w0 * a.y + w1 * b.y + w2 * c.y + w3 * d.y;
    sf.z = w0 * a.z + w1 * b.z + w2 * c.z + w3 * d.z;
    sf.w = w0 * a.w + w1 * b.w + w2 * c.w + w3 * d.w;

    float4 ov;
    ov.x = xv.x * sf.x * sf.x;
    ov.y = xv.y * sf.y * sf.y;
    ov.z = xv.z * sf.z * sf.z;
    ov.w = xv.w * sf.w * sf.w;

    float4* orow = (float4*)(out + (size_t)gwarp * F_CH);
    orow[lane] = ov;
}

extern "C" void kernel_launch(void* const* d_in, const int* in_sizes, int n_in,
                              void* d_out, int out_size)
{
    const float* x    = (const float*)d_in[0];  // eval_x      [B,N,128] f32
    const float* eig  = (const float*)d_in[1];  // eval_eigs   [B,N]     f32
    const float* coef = (const float*)d_in[2];  // filter_coeffs [12,128] f32
    float* out = (float*)d_out;

    int nrows = in_sizes[0] / F_CH;             // B*N = 262144
    int threads = 256;                          // 8 rows per block
    int blocks = (nrows * 32 + threads - 1) / threads;
    spline_filter_kernel<<<blocks, threads>>>(x, eig, coef, out, nrows);
}

// round 2
// speedup vs baseline: 1.4008x; 1.4008x over previous
#include <cuda_runtime.h>

// out[row, f] = x[row, f] * sf^2,  sf = sum_m w_m(t) * coeffs[i-3+m, f]
// i = floor(eig*7.5), t = frac  (uniform knots linspace(0,2,16), cubic
// cardinal B-spline -> exactly 4 nonzero weights).
//
// R2: warp-stride over rows (8 rows/warp) so the shared coeff-table fill is
// amortized 8x; single smem base pointer so the 4 row reads become LDS.128
// with immediate offsets.

#define F_CH 128
#define N_BASES 12
#define PAD_ROWS 18  // padded rows -3..14 -> 0..17; i in [0,14] => i+3 <= 17

__global__ __launch_bounds__(256, 8)
void spline_filter_kernel(const float* __restrict__ x,
                          const float* __restrict__ eig,
                          const float* __restrict__ coef,
                          float* __restrict__ out,
                          int nrows)
{
    __shared__ float sc[PAD_ROWS * F_CH];  // zero-padded coeff table, 9 KB

    // Cooperative fill: padded rows [0,3) and [15,18) zero, rows 3..14 = coeffs.
    #pragma unroll
    for (int idx = threadIdx.x; idx < PAD_ROWS * F_CH; idx += 256) {
        int j = (idx >> 7) - 3;
        sc[idx] = (j >= 0 && j < N_BASES) ? coef[idx - 3 * F_CH] : 0.0f;
    }
    __syncthreads();

    const int lane    = threadIdx.x & 31;
    const int warp0   = (blockIdx.x << 3) + (threadIdx.x >> 5);
    const int wstride = gridDim.x << 3;
    const float* scl  = sc + lane * 4;   // per-lane channel base in smem

    #pragma unroll 2
    for (int row = warp0; row < nrows; row += wstride) {
        // --- basis weights (cheap FFMA chain, replicated per lane) ---
        float e  = __ldg(eig + row);
        float s  = e * 7.5f;
        float fi = floorf(s);
        int   i  = min(max((int)fi, 0), 14);
        float t  = s - (float)i;
        float omt = 1.0f - t;
        float t2  = t * t;
        float w0 = omt * omt * omt * (1.0f / 6.0f);
        float w1 = ((3.0f * t - 6.0f) * t2 + 4.0f) * (1.0f / 6.0f);
        float w2 = (((-3.0f * t + 3.0f) * t + 3.0f) * t + 1.0f) * (1.0f / 6.0f);
        float w3 = t * t2 * (1.0f / 6.0f);

        // --- 4 coeff rows: one base address, immediate LDS.128 offsets ---
        const float4* p = (const float4*)(scl + i * F_CH);
        float4 a = p[0];       // row i
        float4 b = p[32];      // row i+1  (+512 B)
        float4 c = p[64];      // row i+2  (+1024 B)
        float4 d = p[96];      // row i+3  (+1536 B)

        float4 xv = ((const float4*)(x + (size_t)row * F_CH))[lane];

        float4 sf;
        sf.x = w0 * a.x + w1 * b.x + w2 * c.x + w3 * d.x;
        sf.y = w0 * a.y + w1 * b.y + w2 * c.y + w3 * d.y;
        sf.z = w0 * a.z + w1 * b.z + w2 * c.z + w3 * d.z;
        sf.w = w0 * a.w + w1 * b.w + w2 * c.w + w3 * d.w;

        float4 ov;
        ov.x = xv.x * sf.x * sf.x;
        ov.y = xv.y * sf.y * sf.y;
        ov.z = xv.z * sf.z * sf.z;
        ov.w = xv.w * sf.w * sf.w;

        ((float4*)(out + (size_t)row * F_CH))[lane] = ov;
    }
}

extern "C" void kernel_launch(void* const* d_in, const int* in_sizes, int n_in,
                              void* d_out, int out_size)
{
    const float* x    = (const float*)d_in[0];  // eval_x        [B,N,128] f32
    const float* eig  = (const float*)d_in[1];  // eval_eigs     [B,N]     f32
    const float* coef = (const float*)d_in[2];  // filter_coeffs [12,128]  f32
    float* out = (float*)d_out;

    int nrows = in_sizes[0] / F_CH;             // B*N = 262144
    // 8 warps/block, each warp handles ~8 rows -> fill amortized 8x.
    int blocks = (nrows + 63) / 64;             // 4096 for nrows=262144
    if (blocks > 4096) blocks = 4096;
    spline_filter_kernel<<<blocks, 256>>>(x, eig, coef, out, nrows);
}